// round 1
// baseline (speedup 1.0000x reference)
#include <cuda_runtime.h>
#include <math.h>

// Problem constants
#define BB 4
#define TT 2048
#define DM 1024
#define HH 16
#define DH 64
#define MM (BB*TT)          // 8192 rows

// ---------------- scratch (no cudaMalloc allowed) ----------------
__device__ float g_xn  [(size_t)MM*DM];
__device__ float g_q   [(size_t)MM*DM];
__device__ float g_k   [(size_t)MM*DM];
__device__ float g_v   [(size_t)MM*DM];
__device__ float g_a   [(size_t)MM*DM];
__device__ float g_ar  [(size_t)MM*DM];
__device__ float g_beta [(size_t)MM*HH];
__device__ float g_gamma[(size_t)MM*HH];
__device__ float g_o   [(size_t)MM*DM];

__device__ __forceinline__ float sigmoidf_(float x) {
    return 1.0f / (1.0f + expf(-x));
}

// ---------------- LayerNorm: one block per row ----------------
__global__ void ln_kernel(const float* __restrict__ x,
                          const float* __restrict__ w,
                          const float* __restrict__ bsh,
                          float* __restrict__ xn) {
    __shared__ float sh[8];
    const int m = blockIdx.x;
    const int tid = threadIdx.x;
    const float* xr = x + (size_t)m * DM;

    float4 xv = *(const float4*)(xr + tid * 4);
    float s = xv.x + xv.y + xv.z + xv.w;
    #pragma unroll
    for (int o = 16; o; o >>= 1) s += __shfl_xor_sync(0xffffffffu, s, o);
    if ((tid & 31) == 0) sh[tid >> 5] = s;
    __syncthreads();
    float tot = 0.f;
    #pragma unroll
    for (int i = 0; i < 8; i++) tot += sh[i];
    const float mean = tot * (1.0f / 1024.0f);
    __syncthreads();

    float dx0 = xv.x - mean, dx1 = xv.y - mean, dx2 = xv.z - mean, dx3 = xv.w - mean;
    float s2 = dx0*dx0 + dx1*dx1 + dx2*dx2 + dx3*dx3;
    #pragma unroll
    for (int o = 16; o; o >>= 1) s2 += __shfl_xor_sync(0xffffffffu, s2, o);
    if ((tid & 31) == 0) sh[tid >> 5] = s2;
    __syncthreads();
    float tot2 = 0.f;
    #pragma unroll
    for (int i = 0; i < 8; i++) tot2 += sh[i];
    const float rstd = rsqrtf(tot2 * (1.0f / 1024.0f) + 1e-5f);

    float4 wv = *(const float4*)(w + tid * 4);
    float4 bv = *(const float4*)(bsh + tid * 4);
    float4 ov;
    ov.x = dx0 * rstd * wv.x + bv.x;
    ov.y = dx1 * rstd * wv.y + bv.y;
    ov.z = dx2 * rstd * wv.z + bv.z;
    ov.w = dx3 * rstd * wv.w + bv.w;
    *(float4*)(xn + (size_t)m * DM + tid * 4) = ov;
}

// ---------------- fp32 128x128x16 tiled GEMM mainloop ----------------
// C[m,n] = sum_k A[m,k] * W[n,k]   (both row-major, K=1024)
__device__ __forceinline__ void gemm128_mainloop(const float* __restrict__ A,
                                                 const float* __restrict__ W,
                                                 int m0, int n0,
                                                 float acc[8][8],
                                                 int& am_out, int& bn_out) {
    __shared__ float As[2][16][132];
    __shared__ float Bs[2][16][132];

    const int tid = threadIdx.x;
    const int r  = tid >> 2;          // 0..63
    const int kb = (tid & 3) * 4;     // 0,4,8,12

    const float* aP = A + (size_t)(m0 + r) * DM + kb;
    const float* bP = W + (size_t)(n0 + r) * DM + kb;

    const int lane = tid & 31, wp = tid >> 5;
    const int am = (wp >> 1) * 32 + (lane >> 3) * 8;
    const int bn = (wp & 1) * 64 + (lane & 7) * 8;
    am_out = am; bn_out = bn;

    float4 ra0, ra1, rb0, rb1;

    // prologue: tile 0
    {
        const float* ap = aP;
        ra0 = *(const float4*)ap;
        ra1 = *(const float4*)(ap + (size_t)64 * DM);
        const float* bp = bP;
        rb0 = *(const float4*)bp;
        rb1 = *(const float4*)(bp + (size_t)64 * DM);
    }
    {
        As[0][kb+0][r] = ra0.x; As[0][kb+1][r] = ra0.y; As[0][kb+2][r] = ra0.z; As[0][kb+3][r] = ra0.w;
        As[0][kb+0][r+64] = ra1.x; As[0][kb+1][r+64] = ra1.y; As[0][kb+2][r+64] = ra1.z; As[0][kb+3][r+64] = ra1.w;
        Bs[0][kb+0][r] = rb0.x; Bs[0][kb+1][r] = rb0.y; Bs[0][kb+2][r] = rb0.z; Bs[0][kb+3][r] = rb0.w;
        Bs[0][kb+0][r+64] = rb1.x; Bs[0][kb+1][r+64] = rb1.y; Bs[0][kb+2][r+64] = rb1.z; Bs[0][kb+3][r+64] = rb1.w;
    }
    __syncthreads();

    const int nk = DM / 16;  // 64
    for (int kt = 0; kt < nk; kt++) {
        const int bf = kt & 1;
        if (kt < nk - 1) {
            const float* ap = aP + (kt + 1) * 16;
            ra0 = *(const float4*)ap;
            ra1 = *(const float4*)(ap + (size_t)64 * DM);
            const float* bp = bP + (kt + 1) * 16;
            rb0 = *(const float4*)bp;
            rb1 = *(const float4*)(bp + (size_t)64 * DM);
        }
        #pragma unroll
        for (int kk = 0; kk < 16; kk++) {
            float4 a0 = *(const float4*)&As[bf][kk][am];
            float4 a1 = *(const float4*)&As[bf][kk][am + 4];
            float4 b0 = *(const float4*)&Bs[bf][kk][bn];
            float4 b1 = *(const float4*)&Bs[bf][kk][bn + 4];
            float av[8] = {a0.x, a0.y, a0.z, a0.w, a1.x, a1.y, a1.z, a1.w};
            float bv[8] = {b0.x, b0.y, b0.z, b0.w, b1.x, b1.y, b1.z, b1.w};
            #pragma unroll
            for (int i = 0; i < 8; i++)
                #pragma unroll
                for (int j = 0; j < 8; j++)
                    acc[i][j] = fmaf(av[i], bv[j], acc[i][j]);
        }
        if (kt < nk - 1) {
            const int nb = bf ^ 1;
            As[nb][kb+0][r] = ra0.x; As[nb][kb+1][r] = ra0.y; As[nb][kb+2][r] = ra0.z; As[nb][kb+3][r] = ra0.w;
            As[nb][kb+0][r+64] = ra1.x; As[nb][kb+1][r+64] = ra1.y; As[nb][kb+2][r+64] = ra1.z; As[nb][kb+3][r+64] = ra1.w;
            Bs[nb][kb+0][r] = rb0.x; Bs[nb][kb+1][r] = rb0.y; Bs[nb][kb+2][r] = rb0.z; Bs[nb][kb+3][r] = rb0.w;
            Bs[nb][kb+0][r+64] = rb1.x; Bs[nb][kb+1][r+64] = rb1.y; Bs[nb][kb+2][r+64] = rb1.z; Bs[nb][kb+3][r+64] = rb1.w;
        }
        __syncthreads();
    }
}

// ---------------- projection GEMM: xn @ [Wq;Wk;Wv;Wa;WaR]^T ----------------
__global__ void __launch_bounds__(256, 2)
gemm_proj(const float* __restrict__ xn,
          const float* __restrict__ Wq, const float* __restrict__ Wk,
          const float* __restrict__ Wv, const float* __restrict__ Wa,
          const float* __restrict__ War,
          const float* __restrict__ ba, const float* __restrict__ baR) {
    const int m0 = blockIdx.x * 128;
    const int seg = blockIdx.y >> 3;
    const int n0 = (blockIdx.y & 7) * 128;

    const float* Wt; const float* bias = nullptr; float* out;
    if      (seg == 0) { Wt = Wq;  out = g_q; }
    else if (seg == 1) { Wt = Wk;  out = g_k; }
    else if (seg == 2) { Wt = Wv;  out = g_v; }
    else if (seg == 3) { Wt = Wa;  out = g_a;  bias = ba; }
    else               { Wt = War; out = g_ar; bias = baR; }

    float acc[8][8];
    #pragma unroll
    for (int i = 0; i < 8; i++)
        #pragma unroll
        for (int j = 0; j < 8; j++) acc[i][j] = 0.f;

    int am, bn;
    gemm128_mainloop(xn, Wt, m0, n0, acc, am, bn);

    #pragma unroll
    for (int i = 0; i < 8; i++) {
        const int m = m0 + am + i;
        #pragma unroll
        for (int j = 0; j < 8; j++) {
            const int n = n0 + bn + j;
            float vl = acc[i][j];
            if (bias) vl = sigmoidf_(vl + bias[n]);
            out[(size_t)m * DM + n] = vl;
        }
    }
}

// ---------------- output GEMM: o @ Wo^T + residual ----------------
__global__ void __launch_bounds__(256, 2)
gemm_out(const float* __restrict__ ov, const float* __restrict__ Wo,
         const float* __restrict__ xres, float* __restrict__ dout) {
    const int m0 = blockIdx.x * 128;
    const int n0 = blockIdx.y * 128;

    float acc[8][8];
    #pragma unroll
    for (int i = 0; i < 8; i++)
        #pragma unroll
        for (int j = 0; j < 8; j++) acc[i][j] = 0.f;

    int am, bn;
    gemm128_mainloop(ov, Wo, m0, n0, acc, am, bn);

    #pragma unroll
    for (int i = 0; i < 8; i++) {
        const int m = m0 + am + i;
        #pragma unroll
        for (int j = 0; j < 8; j++) {
            const int n = n0 + bn + j;
            dout[(size_t)m * DM + n] = acc[i][j] + xres[(size_t)m * DM + n];
        }
    }
}

// ---------------- beta/gamma head gates (tiny GEMV) ----------------
__global__ void bg_kernel(const float* __restrict__ xn,
                          const float* __restrict__ Wb, const float* __restrict__ bb,
                          const float* __restrict__ Wg, const float* __restrict__ bgm) {
    const int wp = threadIdx.x >> 5, lane = threadIdx.x & 31;
    const int m = blockIdx.x * 8 + wp;
    const float* xr = xn + (size_t)m * DM;
    for (int j = 0; j < HH; j++) {
        const float* wbr = Wb + (size_t)j * DM;
        const float* wgr = Wg + (size_t)j * DM;
        float sb = 0.f, sg = 0.f;
        #pragma unroll 4
        for (int kk = lane * 4; kk < DM; kk += 128) {
            float4 xv = *(const float4*)(xr + kk);
            float4 w1 = *(const float4*)(wbr + kk);
            float4 w2 = *(const float4*)(wgr + kk);
            sb += xv.x*w1.x + xv.y*w1.y + xv.z*w1.z + xv.w*w1.w;
            sg += xv.x*w2.x + xv.y*w2.y + xv.z*w2.z + xv.w*w2.w;
        }
        #pragma unroll
        for (int o = 16; o; o >>= 1) {
            sb += __shfl_xor_sync(0xffffffffu, sb, o);
            sg += __shfl_xor_sync(0xffffffffu, sg, o);
        }
        if (lane == 0) {
            g_beta [(size_t)m * HH + j] = sigmoidf_(sb + bb[j]);
            g_gamma[(size_t)m * HH + j] = sigmoidf_(sg + bgm[j]);
        }
    }
}

// ---------------- sequential scan ----------------
// 128 blocks = (b,h,half); 256 threads; 8 threads/column, 8 state rows each.
__global__ void __launch_bounds__(256, 1)
scan_kernel(const float* __restrict__ Q, const float* __restrict__ K,
            const float* __restrict__ V, const float* __restrict__ A,
            const float* __restrict__ AR,
            const float* __restrict__ Bt, const float* __restrict__ Gt,
            float* __restrict__ O) {
    const int bh = blockIdx.x >> 1;
    const int half = blockIdx.x & 1;
    const int b = bh >> 4, h = bh & 15;
    const int tid = threadIdx.x;
    const int c = tid >> 3;      // column in half-slab (0..31)
    const int r8 = tid & 7;      // row octet
    const int e = half * 32 + c; // column within head (0..63)

    size_t rb  = ((size_t)b * TT) * DM + (size_t)h * DH;   // + t*1024
    const size_t bgb = ((size_t)b * TT) * HH + h;          // + t*16

    __shared__ __align__(16) float sk[2][64], sq[2][64], sv[2][64], sa[2][64], sr[2][64];
    __shared__ float snrm[2][2], sbg[2][2];

    float S[8], R[8];
    #pragma unroll
    for (int i = 0; i < 8; i++) { S[i] = 0.f; R[i] = 0.f; }

    // prefetch assignment
    const int g = tid >> 6, idx = tid & 63;
    const float* p0 = nullptr; const float* p1 = nullptr;
    int s0 = DM, s1 = 0;
    if (g == 0)      { p0 = K + rb + idx; p1 = Q + rb + idx; s1 = DM; }
    else if (g == 1) { p0 = V + rb + idx;
                       if (idx == 0)      { p1 = Bt + bgb; s1 = HH; }
                       else if (idx == 1) { p1 = Gt + bgb; s1 = HH; } }
    else if (g == 2) { p0 = A + rb + idx; }
    else             { p0 = AR + rb + idx; }

    float f0 = *p0;
    float f1 = (s1 ? *p1 : 0.f);

    for (int t = 0; t < TT; t++) {
        const int p = t & 1;
        // ---- store prefetched step t into shared + k-norm partials ----
        if (g == 0) {
            sk[p][idx] = f0; sq[p][idx] = f1;
            float nn = f0 * f0;
            #pragma unroll
            for (int o = 16; o; o >>= 1) nn += __shfl_xor_sync(0xffffffffu, nn, o);
            if ((tid & 31) == 0) snrm[p][tid >> 5] = nn;
        } else if (g == 1) {
            sv[p][idx] = f0;
            if (idx < 2) sbg[p][idx] = f1;
        } else if (g == 2) {
            sa[p][idx] = f0;
        } else {
            sr[p][idx] = f0;
        }
        __syncthreads();

        // ---- prefetch step t+1 (latency overlapped with compute) ----
        if (t + 1 < TT) {
            p0 += s0; f0 = __ldg(p0);
            if (s1) { p1 += s1; f1 = __ldg(p1); }
        }

        // ---- compute ----
        const float nrm2 = snrm[p][0] + snrm[p][1];
        const float invn = 1.0f / fmaxf(sqrtf(nrm2), 1e-12f);

        float4 k0 = *(const float4*)&sk[p][r8 * 8];
        float4 k1 = *(const float4*)&sk[p][r8 * 8 + 4];
        float kn[8] = {k0.x*invn, k0.y*invn, k0.z*invn, k0.w*invn,
                       k1.x*invn, k1.y*invn, k1.z*invn, k1.w*invn};
        float4 q0 = *(const float4*)&sq[p][r8 * 8];
        float4 q1 = *(const float4*)&sq[p][r8 * 8 + 4];
        float qv[8] = {q0.x, q0.y, q0.z, q0.w, q1.x, q1.y, q1.z, q1.w};

        const float beta  = sbg[p][0];
        const float gamma = sbg[p][1];
        const float ve = sv[p][e];

        // pred = S^T kn (column dot)
        float pr = 0.f;
        #pragma unroll
        for (int i = 0; i < 8; i++) pr = fmaf(S[i], kn[i], pr);
        pr += __shfl_xor_sync(0xffffffffu, pr, 1);
        pr += __shfl_xor_sync(0xffffffffu, pr, 2);
        pr += __shfl_xor_sync(0xffffffffu, pr, 4);
        const float re = fminf(fmaxf(ve - pr, -1.0f), 1.0f);

        // S: row-decay, kp = kn^T S, rank-1 update, oS = S^T q
        float4 a0 = *(const float4*)&sa[p][r8 * 8];
        float4 a1 = *(const float4*)&sa[p][r8 * 8 + 4];
        float av[8] = {a0.x, a0.y, a0.z, a0.w, a1.x, a1.y, a1.z, a1.w};
        float kp = 0.f;
        #pragma unroll
        for (int i = 0; i < 8; i++) { S[i] *= av[i]; kp = fmaf(kn[i], S[i], kp); }
        kp += __shfl_xor_sync(0xffffffffu, kp, 1);
        kp += __shfl_xor_sync(0xffffffffu, kp, 2);
        kp += __shfl_xor_sync(0xffffffffu, kp, 4);
        const float cf = beta * (ve - kp);
        float os = 0.f;
        #pragma unroll
        for (int i = 0; i < 8; i++) { S[i] = fmaf(kn[i], cf, S[i]); os = fmaf(S[i], qv[i], os); }

        // R: same with aR, gamma, target re
        float4 r0 = *(const float4*)&sr[p][r8 * 8];
        float4 r1 = *(const float4*)&sr[p][r8 * 8 + 4];
        float rv[8] = {r0.x, r0.y, r0.z, r0.w, r1.x, r1.y, r1.z, r1.w};
        float kr = 0.f;
        #pragma unroll
        for (int i = 0; i < 8; i++) { R[i] *= rv[i]; kr = fmaf(kn[i], R[i], kr); }
        kr += __shfl_xor_sync(0xffffffffu, kr, 1);
        kr += __shfl_xor_sync(0xffffffffu, kr, 2);
        kr += __shfl_xor_sync(0xffffffffu, kr, 4);
        const float cr = gamma * (re - kr);
        #pragma unroll
        for (int i = 0; i < 8; i++) { R[i] = fmaf(kn[i], cr, R[i]); os = fmaf(R[i], qv[i], os); }

        os += __shfl_xor_sync(0xffffffffu, os, 1);
        os += __shfl_xor_sync(0xffffffffu, os, 2);
        os += __shfl_xor_sync(0xffffffffu, os, 4);

        if (r8 == 0) O[rb + e] = os;
        rb += DM;
    }
}

// ---------------- launch ----------------
extern "C" void kernel_launch(void* const* d_in, const int* in_sizes, int n_in,
                              void* d_out, int out_size) {
    const float* x    = (const float*)d_in[0];
    const float* Wq   = (const float*)d_in[1];
    const float* Wk   = (const float*)d_in[2];
    const float* Wv   = (const float*)d_in[3];
    const float* Wa   = (const float*)d_in[4];
    const float* ba   = (const float*)d_in[5];
    const float* Wb   = (const float*)d_in[6];
    const float* bb   = (const float*)d_in[7];
    const float* Wg   = (const float*)d_in[8];
    const float* bgm  = (const float*)d_in[9];
    const float* War  = (const float*)d_in[10];
    const float* baR  = (const float*)d_in[11];
    const float* Wo   = (const float*)d_in[12];
    const float* ln_w = (const float*)d_in[13];
    const float* ln_b = (const float*)d_in[14];
    float* out = (float*)d_out;

    float *xn, *q, *k, *v, *a, *ar, *bet, *gam, *o;
    cudaGetSymbolAddress((void**)&xn,  g_xn);
    cudaGetSymbolAddress((void**)&q,   g_q);
    cudaGetSymbolAddress((void**)&k,   g_k);
    cudaGetSymbolAddress((void**)&v,   g_v);
    cudaGetSymbolAddress((void**)&a,   g_a);
    cudaGetSymbolAddress((void**)&ar,  g_ar);
    cudaGetSymbolAddress((void**)&bet, g_beta);
    cudaGetSymbolAddress((void**)&gam, g_gamma);
    cudaGetSymbolAddress((void**)&o,   g_o);

    ln_kernel<<<MM, 256>>>(x, ln_w, ln_b, xn);
    gemm_proj<<<dim3(MM / 128, 40), 256>>>(xn, Wq, Wk, Wv, Wa, War, ba, baR);
    bg_kernel<<<MM / 8, 256>>>(xn, Wb, bb, Wg, bgm);
    scan_kernel<<<128, 256>>>(q, k, v, a, ar, bet, gam, o);
    gemm_out<<<dim3(MM / 128, DM / 128), 256>>>(o, Wo, x, out);
}

// round 3
// speedup vs baseline: 1.5449x; 1.5449x over previous
#include <cuda_runtime.h>
#include <cuda_bf16.h>
#include <math.h>
#include <stdint.h>

// Problem constants
#define BB 4
#define TT 2048
#define DM 1024
#define HH 16
#define DH 64
#define MM (BB*TT)          // 8192 rows
#define K3 3072             // split-K: [hi | hi | lo] (A)  x  [hi | lo | hi] (W)
#define NWC 6400            // W_cat rows: 5*1024 proj + 16 beta + 16 gamma + 224 pad + 1024 Wo
#define NC 48               // K3 / 64

// ---------------- scratch (no cudaMalloc allowed) ----------------
__device__ __nv_bfloat16 g_acat[(size_t)MM*K3];
__device__ __nv_bfloat16 g_ocat[(size_t)MM*K3];
__device__ __nv_bfloat16 g_wcat[(size_t)NWC*K3];
__device__ float g_q   [(size_t)MM*DM];
__device__ float g_k   [(size_t)MM*DM];
__device__ float g_v   [(size_t)MM*DM];
__device__ float g_a   [(size_t)MM*DM];
__device__ float g_ar  [(size_t)MM*DM];
__device__ float g_beta [(size_t)MM*HH];
__device__ float g_gamma[(size_t)MM*HH];
__device__ float g_o   [(size_t)MM*DM];

__device__ __forceinline__ float sigmoidf_(float x) {
    return 1.0f / (1.0f + expf(-x));
}
__device__ __forceinline__ uint32_t smem_u32(const void* p) {
    return (uint32_t)__cvta_generic_to_shared(p);
}
__device__ __forceinline__ void cp16(uint32_t s, const void* g) {
    asm volatile("cp.async.cg.shared.global [%0], [%1], 16;" :: "r"(s), "l"(g));
}
#define CP_COMMIT() asm volatile("cp.async.commit_group;")
#define CP_WAIT(n)  asm volatile("cp.async.wait_group %0;" :: "n"(n))

#define LDSM_X4(r, addr) \
    asm volatile("ldmatrix.sync.aligned.m8n8.x4.shared.b16 {%0,%1,%2,%3}, [%4];" \
                 : "=r"((r)[0]), "=r"((r)[1]), "=r"((r)[2]), "=r"((r)[3]) : "r"(addr))

#define MMA16816(c, a, b0_, b1_) \
    asm volatile("mma.sync.aligned.m16n8k16.row.col.f32.bf16.bf16.f32 " \
                 "{%0,%1,%2,%3}, {%4,%5,%6,%7}, {%8,%9}, {%0,%1,%2,%3};" \
                 : "+f"((c)[0]), "+f"((c)[1]), "+f"((c)[2]), "+f"((c)[3]) \
                 : "r"((a)[0]), "r"((a)[1]), "r"((a)[2]), "r"((a)[3]), \
                   "r"(b0_), "r"(b1_))

#define GEMM_SMEM (65536 + 1024)

// ---------------- hi/lo split store helper ----------------
__device__ __forceinline__ void store_split(__nv_bfloat16* dst, size_t base, int c,
                                            float4 v, bool a_layout) {
    __nv_bfloat16 h0 = __float2bfloat16(v.x), h1 = __float2bfloat16(v.y);
    __nv_bfloat16 h2 = __float2bfloat16(v.z), h3 = __float2bfloat16(v.w);
    __nv_bfloat16 l0 = __float2bfloat16(v.x - __bfloat162float(h0));
    __nv_bfloat16 l1 = __float2bfloat16(v.y - __bfloat162float(h1));
    __nv_bfloat16 l2 = __float2bfloat16(v.z - __bfloat162float(h2));
    __nv_bfloat16 l3 = __float2bfloat16(v.w - __bfloat162float(h3));
    __nv_bfloat162 hp0; hp0.x = h0; hp0.y = h1;
    __nv_bfloat162 hp1; hp1.x = h2; hp1.y = h3;
    __nv_bfloat162 lp0; lp0.x = l0; lp0.y = l1;
    __nv_bfloat162 lp1; lp1.x = l2; lp1.y = l3;
    __nv_bfloat162* p0 = (__nv_bfloat162*)(dst + base + c);
    __nv_bfloat162* p1 = (__nv_bfloat162*)(dst + base + 1024 + c);
    __nv_bfloat162* p2 = (__nv_bfloat162*)(dst + base + 2048 + c);
    p0[0] = hp0; p0[1] = hp1;
    if (a_layout) { p1[0] = hp0; p1[1] = hp1; p2[0] = lp0; p2[1] = lp1; }
    else          { p1[0] = lp0; p1[1] = lp1; p2[0] = hp0; p2[1] = hp1; }
}

// ---------------- LayerNorm -> A_cat (bf16 hi/hi/lo) ----------------
__global__ void ln_kernel(const float* __restrict__ x,
                          const float* __restrict__ w,
                          const float* __restrict__ bsh) {
    __shared__ float sh[8];
    const int m = blockIdx.x;
    const int tid = threadIdx.x;
    const float* xr = x + (size_t)m * DM;

    float4 xv = *(const float4*)(xr + tid * 4);
    float s = xv.x + xv.y + xv.z + xv.w;
    #pragma unroll
    for (int o = 16; o; o >>= 1) s += __shfl_xor_sync(0xffffffffu, s, o);
    if ((tid & 31) == 0) sh[tid >> 5] = s;
    __syncthreads();
    float tot = 0.f;
    #pragma unroll
    for (int i = 0; i < 8; i++) tot += sh[i];
    const float mean = tot * (1.0f / 1024.0f);
    __syncthreads();

    float dx0 = xv.x - mean, dx1 = xv.y - mean, dx2 = xv.z - mean, dx3 = xv.w - mean;
    float s2 = dx0*dx0 + dx1*dx1 + dx2*dx2 + dx3*dx3;
    #pragma unroll
    for (int o = 16; o; o >>= 1) s2 += __shfl_xor_sync(0xffffffffu, s2, o);
    if ((tid & 31) == 0) sh[tid >> 5] = s2;
    __syncthreads();
    float tot2 = 0.f;
    #pragma unroll
    for (int i = 0; i < 8; i++) tot2 += sh[i];
    const float rstd = rsqrtf(tot2 * (1.0f / 1024.0f) + 1e-5f);

    float4 wv = *(const float4*)(w + tid * 4);
    float4 bv = *(const float4*)(bsh + tid * 4);
    float4 ov;
    ov.x = dx0 * rstd * wv.x + bv.x;
    ov.y = dx1 * rstd * wv.y + bv.y;
    ov.z = dx2 * rstd * wv.z + bv.z;
    ov.w = dx3 * rstd * wv.w + bv.w;

    store_split(g_acat, (size_t)m * K3, tid * 4, ov, true);
}

// ---------------- W_cat builder ----------------
__global__ void conv_w(const float* __restrict__ Wq, const float* __restrict__ Wk,
                       const float* __restrict__ Wv, const float* __restrict__ Wa,
                       const float* __restrict__ War, const float* __restrict__ Wb,
                       const float* __restrict__ Wg, const float* __restrict__ Wo) {
    const int n = blockIdx.x;
    const int c = threadIdx.x * 4;
    float4 v = {0.f, 0.f, 0.f, 0.f};
    const float* src = nullptr;
    if (n < 5120) {
        const int seg = n >> 10;
        const float* tab[5] = {Wq, Wk, Wv, Wa, War};
        src = tab[seg] + (size_t)(n & 1023) * DM;
    } else if (n < 5136) {
        src = Wb + (size_t)(n - 5120) * DM;
    } else if (n < 5152) {
        src = Wg + (size_t)(n - 5136) * DM;
    } else if (n >= 5376) {
        src = Wo + (size_t)(n - 5376) * DM;
    }
    if (src) v = *(const float4*)(src + c);
    store_split(g_wcat, (size_t)n * K3, c, v, false);
}

// ---------------- scan output -> O_cat ----------------
__global__ void conv_o() {
    const int m = blockIdx.x;
    const int c = threadIdx.x * 4;
    float4 v = *(const float4*)(g_o + (size_t)m * DM + c);
    store_split(g_ocat, (size_t)m * K3, c, v, true);
}

// ---------------- epilogue writer (2 consecutive cols) ----------------
__device__ __forceinline__ void epi_write2(int m, int n, float v0, float v1,
        const float* __restrict__ ba, const float* __restrict__ baR,
        const float* __restrict__ bb, const float* __restrict__ bgm,
        const float* __restrict__ xres, float* __restrict__ dout) {
    if (n < 3072) {
        float* outp = (n < 1024) ? g_q : (n < 2048 ? g_k : g_v);
        float2 w; w.x = v0; w.y = v1;
        *(float2*)(outp + (size_t)m * DM + (n & 1023)) = w;
    } else if (n < 5120) {
        float* outp = (n < 4096) ? g_a : g_ar;
        const float* bias = (n < 4096) ? ba : baR;
        const int col = n & 1023;
        float2 w;
        w.x = sigmoidf_(v0 + bias[col]);
        w.y = sigmoidf_(v1 + bias[col + 1]);
        *(float2*)(outp + (size_t)m * DM + col) = w;
    } else if (n < 5136) {
        const int j = n - 5120;
        g_beta[(size_t)m * HH + j]     = sigmoidf_(v0 + bb[j]);
        g_beta[(size_t)m * HH + j + 1] = sigmoidf_(v1 + bb[j + 1]);
    } else if (n < 5152) {
        const int j = n - 5136;
        g_gamma[(size_t)m * HH + j]     = sigmoidf_(v0 + bgm[j]);
        g_gamma[(size_t)m * HH + j + 1] = sigmoidf_(v1 + bgm[j + 1]);
    } else if (n < 5376) {
        // pad: drop
    } else {
        const int col = n - 5376;
        float2 r = *(const float2*)(xres + (size_t)m * DM + col);
        float2 w; w.x = v0 + r.x; w.y = v1 + r.y;
        *(float2*)(dout + (size_t)m * DM + col) = w;
    }
}

// ---------------- mma.sync bf16 GEMM: 128x128 tile, K=3072 ----------------
__global__ void __launch_bounds__(256, 2)
gemm_mma(const __nv_bfloat16* __restrict__ A,
         const __nv_bfloat16* __restrict__ Wc,
         int nbase,
         const float* __restrict__ ba, const float* __restrict__ baR,
         const float* __restrict__ bb, const float* __restrict__ bgm,
         const float* __restrict__ xres, float* __restrict__ dout) {
    extern __shared__ __align__(16) char dsm[];
    const int tid = threadIdx.x;
    const int wid = tid >> 5, lane = tid & 31;
    const int m0 = blockIdx.x * 128;
    const int n0g = nbase + blockIdx.y * 128;

    const uint32_t sbase = smem_u32(dsm);
    const uint32_t tile0 = (sbase + 1023) & ~1023u;
    const uint32_t sA = tile0;
    const uint32_t sW = tile0 + 32768;

    const __nv_bfloat16* Aptr = A + (size_t)m0 * K3;
    const __nv_bfloat16* Wptr = Wc + (size_t)n0g * K3;

    // per-thread copy coords: 4 uint4 each for A and W per chunk
    int cp_r[4], cp_soff[4];
    #pragma unroll
    for (int i = 0; i < 4; i++) {
        const int u = tid + i * 256;
        const int r = u >> 3, c16 = u & 7;
        cp_r[i] = r;
        cp_soff[i] = r * 128 + ((c16 ^ (r & 7)) * 16);
    }

#define ISSUE(cc_) do { \
    const int kc_ = (cc_) * 64; \
    const uint32_t ab_ = sA + ((cc_) & 1) * 16384; \
    const uint32_t wb_ = sW + ((cc_) & 1) * 16384; \
    _Pragma("unroll") \
    for (int i_ = 0; i_ < 4; i_++) { \
        const int c16_ = (tid + i_ * 256) & 7; \
        cp16(ab_ + cp_soff[i_], Aptr + (size_t)cp_r[i_] * K3 + kc_ + c16_ * 8); \
        cp16(wb_ + cp_soff[i_], Wptr + (size_t)cp_r[i_] * K3 + kc_ + c16_ * 8); \
    } \
    CP_COMMIT(); \
} while (0)

    float acc[4][4][4];
    #pragma unroll
    for (int i = 0; i < 4; i++)
        #pragma unroll
        for (int j = 0; j < 4; j++)
            #pragma unroll
            for (int e = 0; e < 4; e++) acc[i][j][e] = 0.f;

    const int mwarp = (wid >> 2) * 64;       // 0 or 64
    const int nwarp = (wid & 3) * 32;        // 0,32,64,96
    const int lrow  = lane & 15;             // row within 16-row frag
    const int lchunk = lane >> 4;            // k-half selector

    ISSUE(0);
    ISSUE(1);

    for (int c = 0; c < NC; c++) {
        if (c + 1 < NC) { CP_WAIT(1); } else { CP_WAIT(0); }
        __syncthreads();

        const uint32_t ab = sA + (c & 1) * 16384;
        const uint32_t wb = sW + (c & 1) * 16384;

        #pragma unroll
        for (int ks = 0; ks < 4; ks++) {
            uint32_t ar[4][4];
            #pragma unroll
            for (int fm = 0; fm < 4; fm++) {
                const int rr = mwarp + fm * 16 + lrow;
                const int cc = ks * 2 + lchunk;
                LDSM_X4(ar[fm], ab + rr * 128 + ((cc ^ (rr & 7)) * 16));
            }
            uint32_t br[2][4];
            #pragma unroll
            for (int g = 0; g < 2; g++) {
                const int rr = nwarp + g * 16 + lrow;
                const int cc = ks * 2 + lchunk;
                LDSM_X4(br[g], wb + rr * 128 + ((cc ^ (rr & 7)) * 16));
            }
            #pragma unroll
            for (int fm = 0; fm < 4; fm++)
                #pragma unroll
                for (int fn = 0; fn < 4; fn++)
                    MMA16816(acc[fm][fn], ar[fm],
                             br[fn >> 1][fn & 1], br[fn >> 1][2 + (fn & 1)]);
        }

        __syncthreads();
        if (c + 2 < NC) ISSUE(c + 2);
    }
#undef ISSUE

    // ---- epilogue ----
    const int mrow_lo = m0 + mwarp + (lane >> 2);
    const int ncol = n0g + nwarp + (lane & 3) * 2;
    #pragma unroll
    for (int fm = 0; fm < 4; fm++) {
        const int m_lo = mrow_lo + fm * 16;
        #pragma unroll
        for (int fn = 0; fn < 4; fn++) {
            const int n = ncol + fn * 8;
            epi_write2(m_lo,     n, acc[fm][fn][0], acc[fm][fn][1], ba, baR, bb, bgm, xres, dout);
            epi_write2(m_lo + 8, n, acc[fm][fn][2], acc[fm][fn][3], ba, baR, bb, bgm, xres, dout);
        }
    }
}

// ---------------- sequential scan (unchanged, passed R1) ----------------
__global__ void __launch_bounds__(256, 1)
scan_kernel(const float* __restrict__ Q, const float* __restrict__ K,
            const float* __restrict__ V, const float* __restrict__ A,
            const float* __restrict__ AR,
            const float* __restrict__ Bt, const float* __restrict__ Gt,
            float* __restrict__ O) {
    const int bh = blockIdx.x >> 1;
    const int half = blockIdx.x & 1;
    const int b = bh >> 4, h = bh & 15;
    const int tid = threadIdx.x;
    const int c = tid >> 3;
    const int r8 = tid & 7;
    const int e = half * 32 + c;

    size_t rb  = ((size_t)b * TT) * DM + (size_t)h * DH;
    const size_t bgb = ((size_t)b * TT) * HH + h;

    __shared__ __align__(16) float sk[2][64], sq[2][64], sv[2][64], sa[2][64], sr[2][64];
    __shared__ float snrm[2][2], sbg[2][2];

    float S[8], R[8];
    #pragma unroll
    for (int i = 0; i < 8; i++) { S[i] = 0.f; R[i] = 0.f; }

    const int g = tid >> 6, idx = tid & 63;
    const float* p0 = nullptr; const float* p1 = nullptr;
    int s0 = DM, s1 = 0;
    if (g == 0)      { p0 = K + rb + idx; p1 = Q + rb + idx; s1 = DM; }
    else if (g == 1) { p0 = V + rb + idx;
                       if (idx == 0)      { p1 = Bt + bgb; s1 = HH; }
                       else if (idx == 1) { p1 = Gt + bgb; s1 = HH; } }
    else if (g == 2) { p0 = A + rb + idx; }
    else             { p0 = AR + rb + idx; }

    float f0 = *p0;
    float f1 = (s1 ? *p1 : 0.f);

    for (int t = 0; t < TT; t++) {
        const int p = t & 1;
        if (g == 0) {
            sk[p][idx] = f0; sq[p][idx] = f1;
            float nn = f0 * f0;
            #pragma unroll
            for (int o = 16; o; o >>= 1) nn += __shfl_xor_sync(0xffffffffu, nn, o);
            if ((tid & 31) == 0) snrm[p][tid >> 5] = nn;
        } else if (g == 1) {
            sv[p][idx] = f0;
            if (idx < 2) sbg[p][idx] = f1;
        } else if (g == 2) {
            sa[p][idx] = f0;
        } else {
            sr[p][idx] = f0;
        }
        __syncthreads();

        if (t + 1 < TT) {
            p0 += s0; f0 = __ldg(p0);
            if (s1) { p1 += s1; f1 = __ldg(p1); }
        }

        const float nrm2 = snrm[p][0] + snrm[p][1];
        const float invn = 1.0f / fmaxf(sqrtf(nrm2), 1e-12f);

        float4 k0 = *(const float4*)&sk[p][r8 * 8];
        float4 k1 = *(const float4*)&sk[p][r8 * 8 + 4];
        float kn[8] = {k0.x*invn, k0.y*invn, k0.z*invn, k0.w*invn,
                       k1.x*invn, k1.y*invn, k1.z*invn, k1.w*invn};
        float4 q0 = *(const float4*)&sq[p][r8 * 8];
        float4 q1 = *(const float4*)&sq[p][r8 * 8 + 4];
        float qv[8] = {q0.x, q0.y, q0.z, q0.w, q1.x, q1.y, q1.z, q1.w};

        const float beta  = sbg[p][0];
        const float gamma = sbg[p][1];
        const float ve = sv[p][e];

        float pr = 0.f;
        #pragma unroll
        for (int i = 0; i < 8; i++) pr = fmaf(S[i], kn[i], pr);
        pr += __shfl_xor_sync(0xffffffffu, pr, 1);
        pr += __shfl_xor_sync(0xffffffffu, pr, 2);
        pr += __shfl_xor_sync(0xffffffffu, pr, 4);
        const float re = fminf(fmaxf(ve - pr, -1.0f), 1.0f);

        float4 a0 = *(const float4*)&sa[p][r8 * 8];
        float4 a1 = *(const float4*)&sa[p][r8 * 8 + 4];
        float av[8] = {a0.x, a0.y, a0.z, a0.w, a1.x, a1.y, a1.z, a1.w};
        float kp = 0.f;
        #pragma unroll
        for (int i = 0; i < 8; i++) { S[i] *= av[i]; kp = fmaf(kn[i], S[i], kp); }
        kp += __shfl_xor_sync(0xffffffffu, kp, 1);
        kp += __shfl_xor_sync(0xffffffffu, kp, 2);
        kp += __shfl_xor_sync(0xffffffffu, kp, 4);
        const float cf = beta * (ve - kp);
        float os = 0.f;
        #pragma unroll
        for (int i = 0; i < 8; i++) { S[i] = fmaf(kn[i], cf, S[i]); os = fmaf(S[i], qv[i], os); }

        float4 r0 = *(const float4*)&sr[p][r8 * 8];
        float4 r1 = *(const float4*)&sr[p][r8 * 8 + 4];
        float rv[8] = {r0.x, r0.y, r0.z, r0.w, r1.x, r1.y, r1.z, r1.w};
        float kr = 0.f;
        #pragma unroll
        for (int i = 0; i < 8; i++) { R[i] *= rv[i]; kr = fmaf(kn[i], R[i], kr); }
        kr += __shfl_xor_sync(0xffffffffu, kr, 1);
        kr += __shfl_xor_sync(0xffffffffu, kr, 2);
        kr += __shfl_xor_sync(0xffffffffu, kr, 4);
        const float cr = gamma * (re - kr);
        #pragma unroll
        for (int i = 0; i < 8; i++) { R[i] = fmaf(kn[i], cr, R[i]); os = fmaf(R[i], qv[i], os); }

        os += __shfl_xor_sync(0xffffffffu, os, 1);
        os += __shfl_xor_sync(0xffffffffu, os, 2);
        os += __shfl_xor_sync(0xffffffffu, os, 4);

        if (r8 == 0) O[rb + e] = os;
        rb += DM;
    }
}

// ---------------- launch ----------------
extern "C" void kernel_launch(void* const* d_in, const int* in_sizes, int n_in,
                              void* d_out, int out_size) {
    const float* x    = (const float*)d_in[0];
    const float* Wq   = (const float*)d_in[1];
    const float* Wk   = (const float*)d_in[2];
    const float* Wv   = (const float*)d_in[3];
    const float* Wa   = (const float*)d_in[4];
    const float* ba   = (const float*)d_in[5];
    const float* Wb   = (const float*)d_in[6];
    const float* bb   = (const float*)d_in[7];
    const float* Wg   = (const float*)d_in[8];
    const float* bgm  = (const float*)d_in[9];
    const float* War  = (const float*)d_in[10];
    const float* baR  = (const float*)d_in[11];
    const float* Wo   = (const float*)d_in[12];
    const float* ln_w = (const float*)d_in[13];
    const float* ln_b = (const float*)d_in[14];
    float* out = (float*)d_out;

    __nv_bfloat16 *acat, *ocat, *wcat;
    float *q, *k, *v, *a, *ar, *bet, *gam, *o;
    cudaGetSymbolAddress((void**)&acat, g_acat);
    cudaGetSymbolAddress((void**)&ocat, g_ocat);
    cudaGetSymbolAddress((void**)&wcat, g_wcat);
    cudaGetSymbolAddress((void**)&q,   g_q);
    cudaGetSymbolAddress((void**)&k,   g_k);
    cudaGetSymbolAddress((void**)&v,   g_v);
    cudaGetSymbolAddress((void**)&a,   g_a);
    cudaGetSymbolAddress((void**)&ar,  g_ar);
    cudaGetSymbolAddress((void**)&bet, g_beta);
    cudaGetSymbolAddress((void**)&gam, g_gamma);
    cudaGetSymbolAddress((void**)&o,   g_o);

    static int smem_set = 0;
    if (!smem_set) {
        cudaFuncSetAttribute(gemm_mma, cudaFuncAttributeMaxDynamicSharedMemorySize, GEMM_SMEM);
        smem_set = 1;
    }

    ln_kernel<<<MM, 256>>>(x, ln_w, ln_b);
    conv_w<<<NWC, 256>>>(Wq, Wk, Wv, Wa, War, Wb, Wg, Wo);
    // proj + head gates: n in [0, 5376)
    gemm_mma<<<dim3(MM/128, 42), 256, GEMM_SMEM>>>(acat, wcat, 0, ba, baR, bb, bgm,
                                                   nullptr, nullptr);
    scan_kernel<<<128, 256>>>(q, k, v, a, ar, bet, gam, o);
    conv_o<<<MM, 256>>>();
    // output proj: n in [5376, 6400)
    gemm_mma<<<dim3(MM/128, 8), 256, GEMM_SMEM>>>(ocat, wcat, 5376, ba, baR, bb, bgm,
                                                  x, out);
}